// round 1
// baseline (speedup 1.0000x reference)
#include <cuda_runtime.h>
#include <cuda_bf16.h>
#include <math.h>

// ---------------- problem constants ----------------
#define TT   128
#define BB   32
#define TB   (TT*BB)          // 4096
#define HID  128
#define FEAT 512
#define AA   18
#define OUTC (AA+1)           // 19

// ---------------- scratch (static device allocations) ----------------
__device__ float g_c1[TB * 32 * 20 * 20];   // 210 MB
__device__ float g_c2[TB * 64 * 9 * 9];     //  85 MB
__device__ float g_c3[TB * 64 * 7 * 7];     //  51 MB
__device__ float g_feat[TB * FEAT];         //   8 MB
__device__ float g_gx[TB * 4 * HID];        //   8 MB
__device__ float g_hid[TB * HID];           //   2 MB

// ============================================================
// conv1: x/255 -> conv(4->32, 8x8, s4) -> relu.  in 84x84, out 20x20
// one CTA per image. smem: image (28224 f) + weights reordered (8192 f)
// ============================================================
__global__ void __launch_bounds__(400, 1)
conv1_kernel(const float* __restrict__ x, const float* __restrict__ w,
             const float* __restrict__ b, float* __restrict__ out)
{
    extern __shared__ float sm[];
    float* img = sm;            // 4*84*84 = 28224
    float* ws  = sm + 28224;    // [r=(ic*8+ky)*8+kx][oc]  8192

    const int n = blockIdx.x, t = threadIdx.x;

    const float4* xg = (const float4*)(x + (size_t)n * 28224);
    float4* img4 = (float4*)img;
    const float inv = 1.0f / 255.0f;
    for (int i = t; i < 7056; i += 400) {
        float4 v = xg[i];
        v.x *= inv; v.y *= inv; v.z *= inv; v.w *= inv;
        img4[i] = v;
    }
    for (int i = t; i < 8192; i += 400) {
        int oc = i & 31, r = i >> 5;
        ws[i] = w[oc * 256 + r];
    }
    __syncthreads();

    const int oy = t / 20, ox = t % 20;
    float acc[32];
#pragma unroll
    for (int oc = 0; oc < 32; ++oc) acc[oc] = b[oc];

#pragma unroll
    for (int ic = 0; ic < 4; ++ic) {
#pragma unroll
        for (int ky = 0; ky < 8; ++ky) {
            const float* row = &img[ic * 7056 + (oy * 4 + ky) * 84 + ox * 4];
            float4 r0 = *(const float4*)row;
            float4 r1 = *(const float4*)(row + 4);
            float rv[8] = {r0.x, r0.y, r0.z, r0.w, r1.x, r1.y, r1.z, r1.w};
            const float* wb = &ws[((ic * 8 + ky) * 8) * 32];
#pragma unroll
            for (int kx = 0; kx < 8; ++kx) {
                float v = rv[kx];
                const float4* w4 = (const float4*)(wb + kx * 32);
#pragma unroll
                for (int q = 0; q < 8; ++q) {
                    float4 wv = w4[q];
                    acc[q * 4 + 0] += v * wv.x;
                    acc[q * 4 + 1] += v * wv.y;
                    acc[q * 4 + 2] += v * wv.z;
                    acc[q * 4 + 3] += v * wv.w;
                }
            }
        }
    }
    float* op = out + (size_t)n * 12800 + t;
#pragma unroll
    for (int oc = 0; oc < 32; ++oc) op[oc * 400] = fmaxf(acc[oc], 0.0f);
}

// ============================================================
// conv2: (32,20,20) -> (64,9,9), 4x4 s2, relu
// 324 threads: 4 oc-groups x 81 positions, 16 oc per thread
// ============================================================
__global__ void __launch_bounds__(324, 1)
conv2_kernel(const float* __restrict__ in, const float* __restrict__ w,
             const float* __restrict__ b, float* __restrict__ out)
{
    extern __shared__ float sm[];
    float* ins = sm;           // 32*400 = 12800
    float* ws  = sm + 12800;   // [r=(ic*4+ky)*4+kx][oc]  32768

    const int n = blockIdx.x, t = threadIdx.x;

    const float4* ig = (const float4*)(in + (size_t)n * 12800);
    float4* is4 = (float4*)ins;
    for (int i = t; i < 3200; i += 324) is4[i] = ig[i];
    for (int i = t; i < 32768; i += 324) {
        int oc = i & 63, r = i >> 6;
        ws[i] = w[oc * 512 + r];
    }
    __syncthreads();

    const int og = t / 81;     // 0..3
    const int p  = t % 81;
    const int oy = p / 9, ox = p % 9;

    float acc[16];
#pragma unroll
    for (int j = 0; j < 16; ++j) acc[j] = b[og * 16 + j];

    for (int ic = 0; ic < 32; ++ic) {
#pragma unroll
        for (int ky = 0; ky < 4; ++ky) {
            const float* row = &ins[ic * 400 + (oy * 2 + ky) * 20 + ox * 2];
            float2 a = *(const float2*)row;
            float2 c = *(const float2*)(row + 2);
            float rv[4] = {a.x, a.y, c.x, c.y};
            const float* wb = &ws[((ic * 4 + ky) * 4) * 64 + og * 16];
#pragma unroll
            for (int kx = 0; kx < 4; ++kx) {
                float v = rv[kx];
                const float4* w4 = (const float4*)(wb + kx * 64);
#pragma unroll
                for (int q = 0; q < 4; ++q) {
                    float4 wv = w4[q];
                    acc[q * 4 + 0] += v * wv.x;
                    acc[q * 4 + 1] += v * wv.y;
                    acc[q * 4 + 2] += v * wv.z;
                    acc[q * 4 + 3] += v * wv.w;
                }
            }
        }
    }
    float* op = out + (size_t)n * 5184 + (size_t)(og * 16) * 81 + p;
#pragma unroll
    for (int j = 0; j < 16; ++j) op[j * 81] = fmaxf(acc[j], 0.0f);
}

// ============================================================
// conv3: (64,9,9) -> (64,7,7), 3x3 s1, relu
// 392 threads: 8 oc-groups x 49 positions, 8 oc per thread
// ============================================================
__global__ void __launch_bounds__(392, 1)
conv3_kernel(const float* __restrict__ in, const float* __restrict__ w,
             const float* __restrict__ b, float* __restrict__ out)
{
    extern __shared__ float sm[];
    float* ins = sm;           // 64*81 = 5184
    float* ws  = sm + 5184;    // [r=ic*9+ky*3+kx][oc]  36864

    const int n = blockIdx.x, t = threadIdx.x;

    const float4* ig = (const float4*)(in + (size_t)n * 5184);
    float4* is4 = (float4*)ins;
    for (int i = t; i < 1296; i += 392) is4[i] = ig[i];
    for (int i = t; i < 36864; i += 392) {
        int oc = i & 63, r = i >> 6;
        ws[i] = w[oc * 576 + r];
    }
    __syncthreads();

    const int og = t / 49;     // 0..7
    const int p  = t % 49;
    const int oy = p / 7, ox = p % 7;

    float acc[8];
#pragma unroll
    for (int j = 0; j < 8; ++j) acc[j] = b[og * 8 + j];

    for (int ic = 0; ic < 64; ++ic) {
#pragma unroll
        for (int ky = 0; ky < 3; ++ky) {
            const float* row = &ins[ic * 81 + (oy + ky) * 9 + ox];
            float rv[3] = {row[0], row[1], row[2]};
            const float* wb = &ws[(ic * 9 + ky * 3) * 64 + og * 8];
#pragma unroll
            for (int kx = 0; kx < 3; ++kx) {
                float v = rv[kx];
                const float4* w4 = (const float4*)(wb + kx * 64);
                float4 w0 = w4[0], w1 = w4[1];
                acc[0] += v * w0.x; acc[1] += v * w0.y;
                acc[2] += v * w0.z; acc[3] += v * w0.w;
                acc[4] += v * w1.x; acc[5] += v * w1.y;
                acc[6] += v * w1.z; acc[7] += v * w1.w;
            }
        }
    }
    float* op = out + (size_t)n * 3136 + (size_t)(og * 8) * 49 + p;
#pragma unroll
    for (int j = 0; j < 8; ++j) op[j * 49] = fmaxf(acc[j], 0.0f);
}

// ============================================================
// GEMM: C[M,N] = A[M,K] @ B[N,K]^T + bias1 (+bias2), optional ReLU
// 128x128x16 tiles, 256 threads, 8x8 micro-tiles.
// M,N multiples of 128; K multiple of 16.
// ============================================================
template <bool RELU, bool BIAS2>
__global__ void __launch_bounds__(256, 2)
gemm_kernel(const float* __restrict__ A, const float* __restrict__ B,
            const float* __restrict__ bias1, const float* __restrict__ bias2,
            float* __restrict__ C, int M, int N, int K)
{
    __shared__ float As[16][128];
    __shared__ float Bs[16][128];

    const int tid = threadIdx.x;
    const int tx = tid & 15, ty = tid >> 4;
    const int bm = blockIdx.y * 128;
    const int bn = blockIdx.x * 128;

    float acc[8][8];
#pragma unroll
    for (int i = 0; i < 8; ++i)
#pragma unroll
        for (int q = 0; q < 8; ++q) acc[i][q] = 0.0f;

    for (int kb = 0; kb < K; kb += 16) {
        // load A,B tiles (transposed into smem: [k][row])
#pragma unroll
        for (int h = 0; h < 2; ++h) {
            int f = tid + h * 256;            // 0..511 float4 slots
            int row = f >> 2, kc4 = (f & 3) * 4;
            float4 av = *(const float4*)(A + (size_t)(bm + row) * K + kb + kc4);
            As[kc4 + 0][row] = av.x; As[kc4 + 1][row] = av.y;
            As[kc4 + 2][row] = av.z; As[kc4 + 3][row] = av.w;
            float4 bv = *(const float4*)(B + (size_t)(bn + row) * K + kb + kc4);
            Bs[kc4 + 0][row] = bv.x; Bs[kc4 + 1][row] = bv.y;
            Bs[kc4 + 2][row] = bv.z; Bs[kc4 + 3][row] = bv.w;
        }
        __syncthreads();

#pragma unroll
        for (int kk = 0; kk < 16; ++kk) {
            float4 a0 = *(const float4*)&As[kk][ty * 8];
            float4 a1 = *(const float4*)&As[kk][ty * 8 + 4];
            float4 b0 = *(const float4*)&Bs[kk][tx * 8];
            float4 b1 = *(const float4*)&Bs[kk][tx * 8 + 4];
            float ar[8] = {a0.x, a0.y, a0.z, a0.w, a1.x, a1.y, a1.z, a1.w};
            float br[8] = {b0.x, b0.y, b0.z, b0.w, b1.x, b1.y, b1.z, b1.w};
#pragma unroll
            for (int i = 0; i < 8; ++i)
#pragma unroll
                for (int q = 0; q < 8; ++q) acc[i][q] += ar[i] * br[q];
        }
        __syncthreads();
    }

    float bv[8];
#pragma unroll
    for (int q = 0; q < 8; ++q) {
        bv[q] = bias1[bn + tx * 8 + q];
        if (BIAS2) bv[q] += bias2[bn + tx * 8 + q];
    }
#pragma unroll
    for (int i = 0; i < 8; ++i) {
        float* cp = C + (size_t)(bm + ty * 8 + i) * N + bn + tx * 8;
#pragma unroll
        for (int q = 0; q < 8; ++q) {
            float v = acc[i][q] + bv[q];
            cp[q] = RELU ? fmaxf(v, 0.0f) : v;
        }
    }
}

// ============================================================
// LSTM recurrence: one CTA per env (32 CTAs), 512 threads,
// thread j owns gate row j (torch order i,f,g,o).
// W_hh[j][0:64] in registers, W_hh[j][64:128] packed in smem.
// gx already holds x@W_ih^T + b_ih + b_hh.
// ============================================================
#define LSTM_SMEM_BYTES (16 * 512 * 16 + 128 * 4 + 512 * 4)

__global__ void __launch_bounds__(512, 1)
lstm_kernel(const float* __restrict__ gx, const float* __restrict__ whh,
            const int* __restrict__ done, const float* __restrict__ h0,
            const float* __restrict__ c0, float* __restrict__ hid)
{
    extern __shared__ float sm[];
    float4* wp4  = (float4*)sm;                    // [16][512] float4
    float*  h_sh = sm + 16 * 512 * 4;              // 128
    float*  act  = h_sh + 128;                     // 512

    const int env = blockIdx.x;
    const int j = threadIdx.x;

    const float* wrow = whh + (size_t)j * 128;
    float wreg[64];
#pragma unroll
    for (int k = 0; k < 64; k += 4) {
        float4 v = *(const float4*)(wrow + k);
        wreg[k] = v.x; wreg[k + 1] = v.y; wreg[k + 2] = v.z; wreg[k + 3] = v.w;
    }
#pragma unroll
    for (int kk = 0; kk < 16; ++kk)
        wp4[kk * 512 + j] = *(const float4*)(wrow + 64 + kk * 4);

    float c = 0.0f, hprev = 0.0f;
    if (j < 128) {
        hprev = h0[env * 128 + j];
        c     = c0[env * 128 + j];
    }
    __syncthreads();

    for (int t = 0; t < TT; ++t) {
        if (j < 128) {
            float m = 1.0f - (float)done[t * BB + env];
            h_sh[j] = hprev * m;
            c *= m;
        }
        __syncthreads();   // S1: masked h ready

        float accv = gx[((size_t)t * BB + env) * 512 + j];
#pragma unroll
        for (int k = 0; k < 64; k += 4) {
            float4 hv = *(const float4*)&h_sh[k];
            accv += hv.x * wreg[k] + hv.y * wreg[k + 1]
                  + hv.z * wreg[k + 2] + hv.w * wreg[k + 3];
        }
#pragma unroll
        for (int kk = 0; kk < 16; ++kk) {
            float4 wv = wp4[kk * 512 + j];
            float4 hv = *(const float4*)&h_sh[64 + kk * 4];
            accv += wv.x * hv.x + wv.y * hv.y + wv.z * hv.z + wv.w * hv.w;
        }

        float a;
        if (j < 256 || j >= 384) a = 1.0f / (1.0f + expf(-accv));  // i,f,o
        else                     a = tanhf(accv);                  // g
        act[j] = a;
        __syncthreads();   // S2: activations ready, all h_sh reads done

        if (j < 128) {
            float ig = act[j],       fg = act[128 + j];
            float gg = act[256 + j], og = act[384 + j];
            c = fg * c + ig * gg;
            hprev = og * tanhf(c);
            hid[((size_t)t * BB + env) * 128 + j] = hprev;
        }
    }
}

// ============================================================
// heads: out[r][0:18] = hid[r] @ wa^T + ba ; out[r][18] = hid[r]@wc^T + bc
// one CTA per 16 rows, 304 threads = 16 rows x 19 cols
// ============================================================
__global__ void __launch_bounds__(304, 4)
heads_kernel(const float* __restrict__ hid, const float* __restrict__ wa,
             const float* __restrict__ ba, const float* __restrict__ wc,
             const float* __restrict__ bc, float* __restrict__ out)
{
    __shared__ float wsh[19 * 128];
    __shared__ float hsh[16 * 128];
    __shared__ float bsh[19];

    const int t = threadIdx.x;
    const int rb = blockIdx.x * 16;

    for (int i = t; i < 18 * 128; i += 304) wsh[i] = wa[i];
    for (int i = t; i < 128; i += 304)      wsh[18 * 128 + i] = wc[i];
    for (int i = t; i < 2048; i += 304)     hsh[i] = hid[(size_t)rb * 128 + i];
    if (t < 18) bsh[t] = ba[t];
    if (t == 18) bsh[18] = bc[0];
    __syncthreads();

    const int r = t / 19, cidx = t % 19;
    float accv = bsh[cidx];
    const float* hr = &hsh[r * 128];
    const float* wr = &wsh[cidx * 128];
#pragma unroll
    for (int k = 0; k < 128; k += 4) {
        float4 hv = *(const float4*)(hr + k);
        float4 wv = *(const float4*)(wr + k);
        accv += hv.x * wv.x + hv.y * wv.y + hv.z * wv.z + hv.w * wv.w;
    }
    out[(size_t)(rb + r) * OUTC + cidx] = accv;
}

// ============================================================
// host launcher
// ============================================================
extern "C" void kernel_launch(void* const* d_in, const int* in_sizes, int n_in,
                              void* d_out, int out_size)
{
    const float* x    = (const float*)d_in[0];
    const int*   done = (const int*)  d_in[1];
    const float* h0   = (const float*)d_in[2];
    const float* c0   = (const float*)d_in[3];
    const float* w1   = (const float*)d_in[4];
    const float* b1   = (const float*)d_in[5];
    const float* w2   = (const float*)d_in[6];
    const float* b2   = (const float*)d_in[7];
    const float* w3   = (const float*)d_in[8];
    const float* b3   = (const float*)d_in[9];
    const float* wf   = (const float*)d_in[10];
    const float* bf   = (const float*)d_in[11];
    const float* w_ih = (const float*)d_in[12];
    const float* w_hh = (const float*)d_in[13];
    const float* b_ih = (const float*)d_in[14];
    const float* b_hh = (const float*)d_in[15];
    const float* wa   = (const float*)d_in[16];
    const float* ba   = (const float*)d_in[17];
    const float* wc   = (const float*)d_in[18];
    const float* bc   = (const float*)d_in[19];
    float* out = (float*)d_out;

    float *c1, *c2, *c3, *feat, *gx, *hidp;
    cudaGetSymbolAddress((void**)&c1,   g_c1);
    cudaGetSymbolAddress((void**)&c2,   g_c2);
    cudaGetSymbolAddress((void**)&c3,   g_c3);
    cudaGetSymbolAddress((void**)&feat, g_feat);
    cudaGetSymbolAddress((void**)&gx,   g_gx);
    cudaGetSymbolAddress((void**)&hidp, g_hid);

    const int c1_smem = (28224 + 8192) * 4;        // 145664
    const int c2_smem = (12800 + 32768) * 4;       // 182272
    const int c3_smem = (5184 + 36864) * 4;        // 168192
    cudaFuncSetAttribute(conv1_kernel, cudaFuncAttributeMaxDynamicSharedMemorySize, c1_smem);
    cudaFuncSetAttribute(conv2_kernel, cudaFuncAttributeMaxDynamicSharedMemorySize, c2_smem);
    cudaFuncSetAttribute(conv3_kernel, cudaFuncAttributeMaxDynamicSharedMemorySize, c3_smem);
    cudaFuncSetAttribute(lstm_kernel,  cudaFuncAttributeMaxDynamicSharedMemorySize, LSTM_SMEM_BYTES);

    conv1_kernel<<<TB, 400, c1_smem>>>(x, w1, b1, c1);
    conv2_kernel<<<TB, 324, c2_smem>>>(c1, w2, b2, c2);
    conv3_kernel<<<TB, 392, c3_smem>>>(c2, w3, b3, c3);

    // feat = relu(c3 @ wf^T + bf)         M=4096 N=512 K=3136
    gemm_kernel<true, false><<<dim3(FEAT / 128, TB / 128), 256>>>(
        c3, wf, bf, nullptr, feat, TB, FEAT, 3136);

    // gx = feat @ w_ih^T + b_ih + b_hh    M=4096 N=512 K=512
    gemm_kernel<false, true><<<dim3(512 / 128, TB / 128), 256>>>(
        feat, w_ih, b_ih, b_hh, gx, TB, 512, FEAT);

    lstm_kernel<<<BB, 512, LSTM_SMEM_BYTES>>>(gx, w_hh, done, h0, c0, hidp);

    heads_kernel<<<TB / 16, 304>>>(hidp, wa, ba, wc, bc, out);
}

// round 2
// speedup vs baseline: 1.0376x; 1.0376x over previous
#include <cuda_runtime.h>
#include <cuda_bf16.h>
#include <math.h>

// ---------------- problem constants ----------------
#define TT   128
#define BB   32
#define TB   (TT*BB)          // 4096
#define HID  128
#define FEAT 512
#define AA   18
#define OUTC (AA+1)           // 19

typedef unsigned long long u64;

// ---------------- packed f32x2 helpers (SASS FFMA2) ----------------
__device__ __forceinline__ u64 pk2(float x, float y) {
    u64 r; asm("mov.b64 %0, {%1, %2};" : "=l"(r) : "f"(x), "f"(y)); return r;
}
__device__ __forceinline__ u64 dup2(float x) { return pk2(x, x); }
__device__ __forceinline__ void ffma2(u64& d, u64 a, u64 b) {
    asm("fma.rn.f32x2 %0, %1, %2, %0;" : "+l"(d) : "l"(a), "l"(b));
}
__device__ __forceinline__ void upk2(u64 v, float& x, float& y) {
    asm("mov.b64 {%0, %1}, %2;" : "=f"(x), "=f"(y) : "l"(v));
}

// ---------------- scratch (static device allocations) ----------------
__device__ float g_c1[TB * 32 * 20 * 20];
__device__ float g_c2[TB * 64 * 9 * 9];
__device__ float g_c3[TB * 64 * 7 * 7];
__device__ float g_feat[TB * FEAT];
__device__ float g_gx[TB * 4 * HID];
__device__ float g_hid[TB * HID];

// ============================================================
// conv1: x/255 -> conv(4->32, 8x8, s4) -> relu.  84x84 -> 20x20
// ============================================================
__global__ void __launch_bounds__(400, 1)
conv1_kernel(const float* __restrict__ x, const float* __restrict__ w,
             const float* __restrict__ b, float* __restrict__ out)
{
    extern __shared__ float sm[];
    float* img = sm;            // 28224
    float* ws  = sm + 28224;    // [r=(ic*8+ky)*8+kx][oc]  8192

    const int n = blockIdx.x, t = threadIdx.x;

    const float4* xg = (const float4*)(x + (size_t)n * 28224);
    float4* img4 = (float4*)img;
    const float inv = 1.0f / 255.0f;
    for (int i = t; i < 7056; i += 400) {
        float4 v = xg[i];
        v.x *= inv; v.y *= inv; v.z *= inv; v.w *= inv;
        img4[i] = v;
    }
    for (int i = t; i < 8192; i += 400) {
        int oc = i & 31, r = i >> 5;
        ws[i] = w[oc * 256 + r];
    }
    __syncthreads();

    const int oy = t / 20, ox = t % 20;
    u64 acc[16];                                // 16 oc-pairs
#pragma unroll
    for (int q = 0; q < 16; ++q) acc[q] = pk2(b[2 * q], b[2 * q + 1]);

#pragma unroll
    for (int ic = 0; ic < 4; ++ic) {
#pragma unroll
        for (int ky = 0; ky < 8; ++ky) {
            const float* row = &img[ic * 7056 + (oy * 4 + ky) * 84 + ox * 4];
            float4 r0 = *(const float4*)row;
            float4 r1 = *(const float4*)(row + 4);
            float rv[8] = {r0.x, r0.y, r0.z, r0.w, r1.x, r1.y, r1.z, r1.w};
            const ulonglong2* wb =
                (const ulonglong2*)&ws[((ic * 8 + ky) * 8) * 32];
#pragma unroll
            for (int kx = 0; kx < 8; ++kx) {
                u64 vv = dup2(rv[kx]);
                const ulonglong2* wk = wb + kx * 8;   // 32 floats = 8 ulonglong2
#pragma unroll
                for (int q = 0; q < 8; ++q) {
                    ulonglong2 wv = wk[q];
                    ffma2(acc[q * 2 + 0], vv, wv.x);
                    ffma2(acc[q * 2 + 1], vv, wv.y);
                }
            }
        }
    }
    float* op = out + (size_t)n * 12800 + t;
#pragma unroll
    for (int q = 0; q < 16; ++q) {
        float a, bv; upk2(acc[q], a, bv);
        op[(2 * q + 0) * 400] = fmaxf(a, 0.0f);
        op[(2 * q + 1) * 400] = fmaxf(bv, 0.0f);
    }
}

// ============================================================
// conv2: (32,20,20) -> (64,9,9), 4x4 s2, relu
// 324 threads: 4 oc-groups x 81 positions, 16 oc per thread
// ============================================================
__global__ void __launch_bounds__(324, 1)
conv2_kernel(const float* __restrict__ in, const float* __restrict__ w,
             const float* __restrict__ b, float* __restrict__ out)
{
    extern __shared__ float sm[];
    float* ins = sm;           // 12800
    float* ws  = sm + 12800;   // [r=(ic*4+ky)*4+kx][oc]  32768

    const int n = blockIdx.x, t = threadIdx.x;

    const float4* ig = (const float4*)(in + (size_t)n * 12800);
    float4* is4 = (float4*)ins;
    for (int i = t; i < 3200; i += 324) is4[i] = ig[i];
    for (int i = t; i < 32768; i += 324) {
        int oc = i & 63, r = i >> 6;
        ws[i] = w[oc * 512 + r];
    }
    __syncthreads();

    const int og = t / 81;     // 0..3
    const int p  = t % 81;
    const int oy = p / 9, ox = p % 9;

    u64 acc[8];                                   // 8 oc-pairs (16 oc)
#pragma unroll
    for (int q = 0; q < 8; ++q)
        acc[q] = pk2(b[og * 16 + 2 * q], b[og * 16 + 2 * q + 1]);

    for (int ic = 0; ic < 32; ++ic) {
#pragma unroll
        for (int ky = 0; ky < 4; ++ky) {
            const float* row = &ins[ic * 400 + (oy * 2 + ky) * 20 + ox * 2];
            float2 a = *(const float2*)row;
            float2 c = *(const float2*)(row + 2);
            float rv[4] = {a.x, a.y, c.x, c.y};
            const float* wb = &ws[((ic * 4 + ky) * 4) * 64 + og * 16];
#pragma unroll
            for (int kx = 0; kx < 4; ++kx) {
                u64 vv = dup2(rv[kx]);
                const ulonglong2* wk = (const ulonglong2*)(wb + kx * 64);
#pragma unroll
                for (int q = 0; q < 4; ++q) {
                    ulonglong2 wv = wk[q];
                    ffma2(acc[q * 2 + 0], vv, wv.x);
                    ffma2(acc[q * 2 + 1], vv, wv.y);
                }
            }
        }
    }
    float* op = out + (size_t)n * 5184 + (size_t)(og * 16) * 81 + p;
#pragma unroll
    for (int q = 0; q < 8; ++q) {
        float a, bv; upk2(acc[q], a, bv);
        op[(2 * q + 0) * 81] = fmaxf(a, 0.0f);
        op[(2 * q + 1) * 81] = fmaxf(bv, 0.0f);
    }
}

// ============================================================
// conv3: (64,9,9) -> (64,7,7), 3x3 s1, relu
// 392 threads: 8 oc-groups x 49 positions, 8 oc per thread
// ============================================================
__global__ void __launch_bounds__(392, 1)
conv3_kernel(const float* __restrict__ in, const float* __restrict__ w,
             const float* __restrict__ b, float* __restrict__ out)
{
    extern __shared__ float sm[];
    float* ins = sm;           // 5184
    float* ws  = sm + 5184;    // [r=ic*9+ky*3+kx][oc]  36864

    const int n = blockIdx.x, t = threadIdx.x;

    const float4* ig = (const float4*)(in + (size_t)n * 5184);
    float4* is4 = (float4*)ins;
    for (int i = t; i < 1296; i += 392) is4[i] = ig[i];
    for (int i = t; i < 36864; i += 392) {
        int oc = i & 63, r = i >> 6;
        ws[i] = w[oc * 576 + r];
    }
    __syncthreads();

    const int og = t / 49;     // 0..7
    const int p  = t % 49;
    const int oy = p / 7, ox = p % 7;

    u64 acc[4];                                   // 4 oc-pairs (8 oc)
#pragma unroll
    for (int q = 0; q < 4; ++q)
        acc[q] = pk2(b[og * 8 + 2 * q], b[og * 8 + 2 * q + 1]);

    for (int ic = 0; ic < 64; ++ic) {
#pragma unroll
        for (int ky = 0; ky < 3; ++ky) {
            const float* row = &ins[ic * 81 + (oy + ky) * 9 + ox];
            float rv[3] = {row[0], row[1], row[2]};
            const float* wb = &ws[(ic * 9 + ky * 3) * 64 + og * 8];
#pragma unroll
            for (int kx = 0; kx < 3; ++kx) {
                u64 vv = dup2(rv[kx]);
                const ulonglong2* wk = (const ulonglong2*)(wb + kx * 64);
                ulonglong2 w0 = wk[0], w1 = wk[1];
                ffma2(acc[0], vv, w0.x);
                ffma2(acc[1], vv, w0.y);
                ffma2(acc[2], vv, w1.x);
                ffma2(acc[3], vv, w1.y);
            }
        }
    }
    float* op = out + (size_t)n * 3136 + (size_t)(og * 8) * 49 + p;
#pragma unroll
    for (int q = 0; q < 4; ++q) {
        float a, bv; upk2(acc[q], a, bv);
        op[(2 * q + 0) * 49] = fmaxf(a, 0.0f);
        op[(2 * q + 1) * 49] = fmaxf(bv, 0.0f);
    }
}

// ============================================================
// GEMM: C[M,N] = A[M,K] @ B[N,K]^T + bias1 (+bias2), optional ReLU
// 128x64 tiles, 256 threads, 8(M)x4(N) micro-tiles, f32x2 FMA.
// M mult of 128, N mult of 64, K mult of 16.
// ============================================================
template <bool RELU, bool BIAS2>
__global__ void __launch_bounds__(256, 3)
gemm_kernel(const float* __restrict__ A, const float* __restrict__ B,
            const float* __restrict__ bias1, const float* __restrict__ bias2,
            float* __restrict__ C, int M, int N, int K)
{
    __shared__ float As[16][128];
    __shared__ float Bs[16][64];

    const int tid = threadIdx.x;
    const int tx = tid & 15, ty = tid >> 4;      // tx: N-group, ty: M-group
    const int bm = blockIdx.y * 128;
    const int bn = blockIdx.x * 64;

    u64 acc[4][4];                               // [M-pair][N col]
#pragma unroll
    for (int i = 0; i < 4; ++i)
#pragma unroll
        for (int q = 0; q < 4; ++q) acc[i][q] = 0ull;

    for (int kb = 0; kb < K; kb += 16) {
        // A tile: 512 float4 slots, 2 per thread
#pragma unroll
        for (int h = 0; h < 2; ++h) {
            int f = tid + h * 256;
            int row = f >> 2, kc4 = (f & 3) * 4;
            float4 av = *(const float4*)(A + (size_t)(bm + row) * K + kb + kc4);
            As[kc4 + 0][row] = av.x; As[kc4 + 1][row] = av.y;
            As[kc4 + 2][row] = av.z; As[kc4 + 3][row] = av.w;
        }
        // B tile: 256 float4 slots, 1 per thread
        {
            int row = tid >> 2, kc4 = (tid & 3) * 4;
            float4 bv = *(const float4*)(B + (size_t)(bn + row) * K + kb + kc4);
            Bs[kc4 + 0][row] = bv.x; Bs[kc4 + 1][row] = bv.y;
            Bs[kc4 + 2][row] = bv.z; Bs[kc4 + 3][row] = bv.w;
        }
        __syncthreads();

#pragma unroll
        for (int kk = 0; kk < 16; ++kk) {
            ulonglong2 a01 = *(const ulonglong2*)&As[kk][ty * 8];
            ulonglong2 a23 = *(const ulonglong2*)&As[kk][ty * 8 + 4];
            float4 bv = *(const float4*)&Bs[kk][tx * 4];
            u64 b0 = dup2(bv.x), b1 = dup2(bv.y), b2 = dup2(bv.z), b3 = dup2(bv.w);
            ffma2(acc[0][0], a01.x, b0); ffma2(acc[0][1], a01.x, b1);
            ffma2(acc[0][2], a01.x, b2); ffma2(acc[0][3], a01.x, b3);
            ffma2(acc[1][0], a01.y, b0); ffma2(acc[1][1], a01.y, b1);
            ffma2(acc[1][2], a01.y, b2); ffma2(acc[1][3], a01.y, b3);
            ffma2(acc[2][0], a23.x, b0); ffma2(acc[2][1], a23.x, b1);
            ffma2(acc[2][2], a23.x, b2); ffma2(acc[2][3], a23.x, b3);
            ffma2(acc[3][0], a23.y, b0); ffma2(acc[3][1], a23.y, b1);
            ffma2(acc[3][2], a23.y, b2); ffma2(acc[3][3], a23.y, b3);
        }
        __syncthreads();
    }

    float bv[4];
#pragma unroll
    for (int q = 0; q < 4; ++q) {
        bv[q] = bias1[bn + tx * 4 + q];
        if (BIAS2) bv[q] += bias2[bn + tx * 4 + q];
    }
#pragma unroll
    for (int i = 0; i < 4; ++i) {
        float lo[4], hi[4];
#pragma unroll
        for (int q = 0; q < 4; ++q) {
            upk2(acc[i][q], lo[q], hi[q]);
            lo[q] += bv[q]; hi[q] += bv[q];
            if (RELU) { lo[q] = fmaxf(lo[q], 0.0f); hi[q] = fmaxf(hi[q], 0.0f); }
        }
        float* c0 = C + (size_t)(bm + ty * 8 + 2 * i) * N + bn + tx * 4;
        float* c1 = c0 + N;
        *(float4*)c0 = make_float4(lo[0], lo[1], lo[2], lo[3]);
        *(float4*)c1 = make_float4(hi[0], hi[1], hi[2], hi[3]);
    }
}

// ============================================================
// LSTM recurrence: one CTA per env (32 CTAs), 512 threads.
// ============================================================
#define LSTM_SMEM_BYTES (16 * 512 * 16 + 128 * 4 + 512 * 4)

__global__ void __launch_bounds__(512, 1)
lstm_kernel(const float* __restrict__ gx, const float* __restrict__ whh,
            const int* __restrict__ done, const float* __restrict__ h0,
            const float* __restrict__ c0, float* __restrict__ hid)
{
    extern __shared__ float sm[];
    float4* wp4  = (float4*)sm;                    // [16][512] float4
    float*  h_sh = sm + 16 * 512 * 4;              // 128
    float*  act  = h_sh + 128;                     // 512

    const int env = blockIdx.x;
    const int j = threadIdx.x;

    const float* wrow = whh + (size_t)j * 128;
    float wreg[64];
#pragma unroll
    for (int k = 0; k < 64; k += 4) {
        float4 v = *(const float4*)(wrow + k);
        wreg[k] = v.x; wreg[k + 1] = v.y; wreg[k + 2] = v.z; wreg[k + 3] = v.w;
    }
#pragma unroll
    for (int kk = 0; kk < 16; ++kk)
        wp4[kk * 512 + j] = *(const float4*)(wrow + 64 + kk * 4);

    float c = 0.0f, hprev = 0.0f;
    if (j < 128) {
        hprev = h0[env * 128 + j];
        c     = c0[env * 128 + j];
    }
    __syncthreads();

    for (int t = 0; t < TT; ++t) {
        if (j < 128) {
            float m = 1.0f - (float)done[t * BB + env];
            h_sh[j] = hprev * m;
            c *= m;
        }
        __syncthreads();

        float accv = gx[((size_t)t * BB + env) * 512 + j];
#pragma unroll
        for (int k = 0; k < 64; k += 4) {
            float4 hv = *(const float4*)&h_sh[k];
            accv += hv.x * wreg[k] + hv.y * wreg[k + 1]
                  + hv.z * wreg[k + 2] + hv.w * wreg[k + 3];
        }
#pragma unroll
        for (int kk = 0; kk < 16; ++kk) {
            float4 wv = wp4[kk * 512 + j];
            float4 hv = *(const float4*)&h_sh[64 + kk * 4];
            accv += wv.x * hv.x + wv.y * hv.y + wv.z * hv.z + wv.w * hv.w;
        }

        float a;
        if (j < 256 || j >= 384) a = 1.0f / (1.0f + expf(-accv));
        else                     a = tanhf(accv);
        act[j] = a;
        __syncthreads();

        if (j < 128) {
            float ig = act[j],       fg = act[128 + j];
            float gg = act[256 + j], og = act[384 + j];
            c = fg * c + ig * gg;
            hprev = og * tanhf(c);
            hid[((size_t)t * BB + env) * 128 + j] = hprev;
        }
    }
}

// ============================================================
// heads
// ============================================================
__global__ void __launch_bounds__(304, 4)
heads_kernel(const float* __restrict__ hid, const float* __restrict__ wa,
             const float* __restrict__ ba, const float* __restrict__ wc,
             const float* __restrict__ bc, float* __restrict__ out)
{
    __shared__ float wsh[19 * 128];
    __shared__ float hsh[16 * 128];
    __shared__ float bsh[19];

    const int t = threadIdx.x;
    const int rb = blockIdx.x * 16;

    for (int i = t; i < 18 * 128; i += 304) wsh[i] = wa[i];
    for (int i = t; i < 128; i += 304)      wsh[18 * 128 + i] = wc[i];
    for (int i = t; i < 2048; i += 304)     hsh[i] = hid[(size_t)rb * 128 + i];
    if (t < 18) bsh[t] = ba[t];
    if (t == 18) bsh[18] = bc[0];
    __syncthreads();

    const int r = t / 19, cidx = t % 19;
    float accv = bsh[cidx];
    const float* hr = &hsh[r * 128];
    const float* wr = &wsh[cidx * 128];
#pragma unroll
    for (int k = 0; k < 128; k += 4) {
        float4 hv = *(const float4*)(hr + k);
        float4 wv = *(const float4*)(wr + k);
        accv += hv.x * wv.x + hv.y * wv.y + hv.z * wv.z + hv.w * wv.w;
    }
    out[(size_t)(rb + r) * OUTC + cidx] = accv;
}

// ============================================================
// host launcher
// ============================================================
extern "C" void kernel_launch(void* const* d_in, const int* in_sizes, int n_in,
                              void* d_out, int out_size)
{
    const float* x    = (const float*)d_in[0];
    const int*   done = (const int*)  d_in[1];
    const float* h0   = (const float*)d_in[2];
    const float* c0   = (const float*)d_in[3];
    const float* w1   = (const float*)d_in[4];
    const float* b1   = (const float*)d_in[5];
    const float* w2   = (const float*)d_in[6];
    const float* b2   = (const float*)d_in[7];
    const float* w3   = (const float*)d_in[8];
    const float* b3   = (const float*)d_in[9];
    const float* wf   = (const float*)d_in[10];
    const float* bf   = (const float*)d_in[11];
    const float* w_ih = (const float*)d_in[12];
    const float* w_hh = (const float*)d_in[13];
    const float* b_ih = (const float*)d_in[14];
    const float* b_hh = (const float*)d_in[15];
    const float* wa   = (const float*)d_in[16];
    const float* ba   = (const float*)d_in[17];
    const float* wc   = (const float*)d_in[18];
    const float* bc   = (const float*)d_in[19];
    float* out = (float*)d_out;

    float *c1, *c2, *c3, *feat, *gx, *hidp;
    cudaGetSymbolAddress((void**)&c1,   g_c1);
    cudaGetSymbolAddress((void**)&c2,   g_c2);
    cudaGetSymbolAddress((void**)&c3,   g_c3);
    cudaGetSymbolAddress((void**)&feat, g_feat);
    cudaGetSymbolAddress((void**)&gx,   g_gx);
    cudaGetSymbolAddress((void**)&hidp, g_hid);

    const int c1_smem = (28224 + 8192) * 4;
    const int c2_smem = (12800 + 32768) * 4;
    const int c3_smem = (5184 + 36864) * 4;
    cudaFuncSetAttribute(conv1_kernel, cudaFuncAttributeMaxDynamicSharedMemorySize, c1_smem);
    cudaFuncSetAttribute(conv2_kernel, cudaFuncAttributeMaxDynamicSharedMemorySize, c2_smem);
    cudaFuncSetAttribute(conv3_kernel, cudaFuncAttributeMaxDynamicSharedMemorySize, c3_smem);
    cudaFuncSetAttribute(lstm_kernel,  cudaFuncAttributeMaxDynamicSharedMemorySize, LSTM_SMEM_BYTES);

    conv1_kernel<<<TB, 400, c1_smem>>>(x, w1, b1, c1);
    conv2_kernel<<<TB, 324, c2_smem>>>(c1, w2, b2, c2);
    conv3_kernel<<<TB, 392, c3_smem>>>(c2, w3, b3, c3);

    // feat = relu(c3 @ wf^T + bf)         M=4096 N=512 K=3136
    gemm_kernel<true, false><<<dim3(FEAT / 64, TB / 128), 256>>>(
        c3, wf, bf, nullptr, feat, TB, FEAT, 3136);

    // gx = feat @ w_ih^T + b_ih + b_hh    M=4096 N=512 K=512
    gemm_kernel<false, true><<<dim3(512 / 64, TB / 128), 256>>>(
        feat, w_ih, b_ih, b_hh, gx, TB, 512, FEAT);

    lstm_kernel<<<BB, 512, LSTM_SMEM_BYTES>>>(gx, w_hh, done, h0, c0, hidp);

    heads_kernel<<<TB / 16, 304>>>(hidp, wa, ba, wc, bc, out);
}

// round 3
// speedup vs baseline: 1.9958x; 1.9235x over previous
#include <cuda_runtime.h>
#include <cuda_bf16.h>
#include <math.h>

// ---------------- problem constants ----------------
#define TT   128
#define BB   32
#define TB   (TT*BB)          // 4096
#define HID  128
#define FEAT 512
#define AA   18
#define OUTC (AA+1)           // 19

typedef unsigned long long u64;

// ---------------- packed f32x2 helpers (SASS FFMA2) ----------------
__device__ __forceinline__ u64 pk2(float x, float y) {
    u64 r; asm("mov.b64 %0, {%1, %2};" : "=l"(r) : "f"(x), "f"(y)); return r;
}
__device__ __forceinline__ u64 dup2(float x) { return pk2(x, x); }
__device__ __forceinline__ void ffma2(u64& d, u64 a, u64 b) {
    asm("fma.rn.f32x2 %0, %1, %2, %0;" : "+l"(d) : "l"(a), "l"(b));
}
__device__ __forceinline__ void upk2(u64 v, float& x, float& y) {
    asm("mov.b64 {%0, %1}, %2;" : "=f"(x), "=f"(y) : "l"(v));
}

// ---------------- scratch (static device allocations) ----------------
__device__ float g_c1[TB * 32 * 20 * 20];
__device__ float g_c2[TB * 64 * 9 * 9];
__device__ float g_c3[TB * 64 * 7 * 7];
__device__ float g_feat[TB * FEAT];
__device__ float g_gx[TB * 4 * HID];
__device__ float g_hid[TB * HID];
__device__ float g_w1r[8192];    // conv1 weights reordered [r=256][oc=32], pre-scaled 1/255
__device__ float g_w2r[32768];   // conv2 [r=512][oc=64]
__device__ float g_w3r[36864];   // conv3 [r=576][oc=64]

// ============================================================
// weight reorder: out[r*OC + oc] = in[oc*R + r] * scale
// ============================================================
__global__ void reorder_w_kernel(const float* __restrict__ in,
                                 float* __restrict__ out,
                                 int R, int OC, float scale)
{
    int i = blockIdx.x * 256 + threadIdx.x;
    if (i >= R * OC) return;
    int oc = i / R, r = i - oc * R;     // consecutive tid -> consecutive r (coalesced read)
    out[r * OC + oc] = in[oc * R + r] * scale;
}

// ============================================================
// conv1: conv(4->32, 8x8, s4) -> relu.  84x84 -> 20x20
// weights pre-scaled by 1/255 (folds x/255).
// 512 threads: ocg = tid>>7 (4 groups of 8 oc), p = tid&127 (<100 active),
// p -> (oy = p/5, xg = p%5); thread computes 4 positions ox = xg*4+{0..3}.
// ============================================================
__global__ void __launch_bounds__(512, 1)
conv1_kernel(const float* __restrict__ x, const float* __restrict__ wr,
             const float* __restrict__ b, float* __restrict__ out)
{
    extern __shared__ float sm[];
    float* img = sm;            // 28224
    float* ws  = sm + 28224;    // [r=(ic*8+ky)*8+kx][oc=32]  8192

    const int n = blockIdx.x, t = threadIdx.x;

    const float4* xg4 = (const float4*)(x + (size_t)n * 28224);
    float4* img4 = (float4*)img;
#pragma unroll 4
    for (int i = t; i < 7056; i += 512) img4[i] = xg4[i];
    const float4* wg = (const float4*)wr;
    float4* ws4 = (float4*)ws;
#pragma unroll
    for (int i = t; i < 2048; i += 512) ws4[i] = wg[i];
    __syncthreads();

    const int ocg = t >> 7, p = t & 127;
    if (p >= 100) return;
    const int oy = p / 5, xg = p % 5;

    u64 acc[4][4];   // [pos i][oc-pair q]
#pragma unroll
    for (int q = 0; q < 4; ++q) {
        u64 bq = pk2(b[ocg * 8 + 2 * q], b[ocg * 8 + 2 * q + 1]);
#pragma unroll
        for (int i = 0; i < 4; ++i) acc[i][q] = bq;
    }

    for (int ic = 0; ic < 4; ++ic) {
#pragma unroll
        for (int ky = 0; ky < 8; ++ky) {
            const float* row = &img[ic * 7056 + (oy * 4 + ky) * 84 + xg * 16];
            float rv[20];
#pragma unroll
            for (int j = 0; j < 5; ++j)
                *(float4*)&rv[j * 4] = *(const float4*)&row[j * 4];
            const float* wb = &ws[((ic * 8 + ky) * 8) * 32 + ocg * 8];
#pragma unroll
            for (int kx = 0; kx < 8; ++kx) {
                ulonglong2 w01 = *(const ulonglong2*)&wb[kx * 32];
                ulonglong2 w23 = *(const ulonglong2*)&wb[kx * 32 + 4];
#pragma unroll
                for (int i = 0; i < 4; ++i) {
                    u64 v = dup2(rv[i * 4 + kx]);
                    ffma2(acc[i][0], v, w01.x);
                    ffma2(acc[i][1], v, w01.y);
                    ffma2(acc[i][2], v, w23.x);
                    ffma2(acc[i][3], v, w23.y);
                }
            }
        }
    }
    float* op = out + (size_t)n * 12800 + oy * 20 + xg * 4;
#pragma unroll
    for (int q = 0; q < 4; ++q) {
#pragma unroll
        for (int i = 0; i < 4; ++i) {
            float lo, hi; upk2(acc[i][q], lo, hi);
            op[(ocg * 8 + 2 * q + 0) * 400 + i] = fmaxf(lo, 0.0f);
            op[(ocg * 8 + 2 * q + 1) * 400 + i] = fmaxf(hi, 0.0f);
        }
    }
}

// ============================================================
// conv2: (32,20,20) -> (64,9,9), 4x4 s2, relu
// 256 threads: ocg = tid>>5 (8 groups of 8 oc), sp = tid&31 (<27 active),
// sp -> (oy = sp/3, xg = sp%3); 3 positions ox = xg*3+{0..2}.
// 4 images processed sequentially per CTA (weights loaded once).
// ============================================================
__global__ void __launch_bounds__(256, 1)
conv2_kernel(const float* __restrict__ in, const float* __restrict__ wr,
             const float* __restrict__ b, float* __restrict__ out)
{
    extern __shared__ float sm[];
    float* ws  = sm;            // [r=(ic*4+ky)*4+kx][oc=64]  32768
    float* img = sm + 32768;    // 12800

    const int t = threadIdx.x;
    const float4* wg = (const float4*)wr;
    float4* ws4 = (float4*)ws;
#pragma unroll
    for (int i = t; i < 8192; i += 256) ws4[i] = wg[i];

    const int ocg = t >> 5, sp = t & 31;
    const bool act = sp < 27;
    const int oy = sp / 3, xg = sp % 3;

    u64 bia[4];
#pragma unroll
    for (int q = 0; q < 4; ++q)
        bia[q] = pk2(b[ocg * 8 + 2 * q], b[ocg * 8 + 2 * q + 1]);

    for (int im = 0; im < 4; ++im) {
        const int n = blockIdx.x * 4 + im;
        __syncthreads();   // previous round's readers done before overwrite
        const float4* ig = (const float4*)(in + (size_t)n * 12800);
        float4* img4 = (float4*)img;
#pragma unroll
        for (int i = t; i < 3200; i += 256) img4[i] = ig[i];
        __syncthreads();

        if (act) {
            u64 acc[3][4];
#pragma unroll
            for (int i = 0; i < 3; ++i)
#pragma unroll
                for (int q = 0; q < 4; ++q) acc[i][q] = bia[q];

            for (int ic = 0; ic < 32; ++ic) {
#pragma unroll
                for (int ky = 0; ky < 4; ++ky) {
                    const float* row = &img[ic * 400 + (oy * 2 + ky) * 20 + xg * 6];
                    float rv[8];
#pragma unroll
                    for (int j = 0; j < 4; ++j)
                        *(float2*)&rv[j * 2] = *(const float2*)&row[j * 2];
                    const float* wb = &ws[((ic * 4 + ky) * 4) * 64 + ocg * 8];
#pragma unroll
                    for (int kx = 0; kx < 4; ++kx) {
                        ulonglong2 w01 = *(const ulonglong2*)&wb[kx * 64];
                        ulonglong2 w23 = *(const ulonglong2*)&wb[kx * 64 + 4];
#pragma unroll
                        for (int i = 0; i < 3; ++i) {
                            u64 v = dup2(rv[i * 2 + kx]);
                            ffma2(acc[i][0], v, w01.x);
                            ffma2(acc[i][1], v, w01.y);
                            ffma2(acc[i][2], v, w23.x);
                            ffma2(acc[i][3], v, w23.y);
                        }
                    }
                }
            }
            float* op = out + (size_t)n * 5184 + oy * 9 + xg * 3;
#pragma unroll
            for (int q = 0; q < 4; ++q) {
#pragma unroll
                for (int i = 0; i < 3; ++i) {
                    float lo, hi; upk2(acc[i][q], lo, hi);
                    op[(ocg * 8 + 2 * q + 0) * 81 + i] = fmaxf(lo, 0.0f);
                    op[(ocg * 8 + 2 * q + 1) * 81 + i] = fmaxf(hi, 0.0f);
                }
            }
        }
    }
}

// ============================================================
// conv3: (64,9,9) -> (64,7,7), 3x3 s1, relu
// 256 threads: ocg = tid>>4 (16 groups of 4 oc), sub = tid&15,
// img2 = sub>>3 (2 concurrent images), oy = sub&7 (<7 active).
// Thread computes all 7 ox. 2 rounds x 2 images = 4 images per CTA.
// ============================================================
__global__ void __launch_bounds__(256, 1)
conv3_kernel(const float* __restrict__ in, const float* __restrict__ wr,
             const float* __restrict__ b, float* __restrict__ out)
{
    extern __shared__ float sm[];
    float* ws  = sm;            // [r=ic*9+ky*3+kx][oc=64]  36864
    float* img = sm + 36864;    // 2*5184

    const int t = threadIdx.x;
    const float4* wg = (const float4*)wr;
    float4* ws4 = (float4*)ws;
#pragma unroll
    for (int i = t; i < 9216; i += 256) ws4[i] = wg[i];

    const int ocg = t >> 4, sub = t & 15;
    const int img2 = sub >> 3, oy = sub & 7;
    const bool act = oy < 7;

    u64 bia[2];
    bia[0] = pk2(b[ocg * 4 + 0], b[ocg * 4 + 1]);
    bia[1] = pk2(b[ocg * 4 + 2], b[ocg * 4 + 3]);

    for (int round = 0; round < 2; ++round) {
        const int n = blockIdx.x * 4 + round * 2;   // images n, n+1
        __syncthreads();
        const float4* ig = (const float4*)(in + (size_t)n * 5184);
        float4* img4 = (float4*)img;
#pragma unroll
        for (int i = t; i < 2592; i += 256) img4[i] = ig[i];
        __syncthreads();

        if (act) {
            const float* ib = &img[img2 * 5184];
            u64 acc[7][2];
#pragma unroll
            for (int i = 0; i < 7; ++i) { acc[i][0] = bia[0]; acc[i][1] = bia[1]; }

            for (int ic = 0; ic < 64; ++ic) {
#pragma unroll
                for (int ky = 0; ky < 3; ++ky) {
                    const float* row = &ib[ic * 81 + (oy + ky) * 9];
                    u64 rd[9];
#pragma unroll
                    for (int c = 0; c < 9; ++c) rd[c] = dup2(row[c]);
                    const float* wb = &ws[(ic * 9 + ky * 3) * 64 + ocg * 4];
#pragma unroll
                    for (int kx = 0; kx < 3; ++kx) {
                        ulonglong2 wv = *(const ulonglong2*)&wb[kx * 64];
#pragma unroll
                        for (int ox = 0; ox < 7; ++ox) {
                            ffma2(acc[ox][0], rd[ox + kx], wv.x);
                            ffma2(acc[ox][1], rd[ox + kx], wv.y);
                        }
                    }
                }
            }
            float* op = out + (size_t)(n + img2) * 3136 + oy * 7;
#pragma unroll
            for (int q = 0; q < 2; ++q) {
#pragma unroll
                for (int ox = 0; ox < 7; ++ox) {
                    float lo, hi; upk2(acc[ox][q], lo, hi);
                    op[(ocg * 4 + 2 * q + 0) * 49 + ox] = fmaxf(lo, 0.0f);
                    op[(ocg * 4 + 2 * q + 1) * 49 + ox] = fmaxf(hi, 0.0f);
                }
            }
        }
    }
}

// ============================================================
// GEMM: C[M,N] = A[M,K] @ B[N,K]^T + bias1 (+bias2), optional ReLU
// 128x64 tiles, 128 threads, 8(M)x8(N) micro-tiles, f32x2 FMA.
// ratio: 32 FFMA2 : 4 LDS.128 per kk = 8:1 (crossbar-balanced).
// ============================================================
template <bool RELU, bool BIAS2>
__global__ void __launch_bounds__(128, 4)
gemm_kernel(const float* __restrict__ A, const float* __restrict__ B,
            const float* __restrict__ bias1, const float* __restrict__ bias2,
            float* __restrict__ C, int M, int N, int K)
{
    __shared__ float As[16][128];
    __shared__ float Bs[16][64];

    const int tid = threadIdx.x;
    const int tx = tid & 7, ty = tid >> 3;       // tx: N-group(8), ty: M-group(16)
    const int bm = blockIdx.y * 128;
    const int bn = blockIdx.x * 64;

    u64 acc[4][8];
#pragma unroll
    for (int i = 0; i < 4; ++i)
#pragma unroll
        for (int q = 0; q < 8; ++q) acc[i][q] = 0ull;

    for (int kb = 0; kb < K; kb += 16) {
#pragma unroll
        for (int h = 0; h < 4; ++h) {           // A: 512 float4 slots
            int f = tid + h * 128;
            int row = f >> 2, kc4 = (f & 3) * 4;
            float4 av = *(const float4*)(A + (size_t)(bm + row) * K + kb + kc4);
            As[kc4 + 0][row] = av.x; As[kc4 + 1][row] = av.y;
            As[kc4 + 2][row] = av.z; As[kc4 + 3][row] = av.w;
        }
#pragma unroll
        for (int h = 0; h < 2; ++h) {           // B: 256 float4 slots
            int f = tid + h * 128;
            int row = f >> 2, kc4 = (f & 3) * 4;
            float4 bv = *(const float4*)(B + (size_t)(bn + row) * K + kb + kc4);
            Bs[kc4 + 0][row] = bv.x; Bs[kc4 + 1][row] = bv.y;
            Bs[kc4 + 2][row] = bv.z; Bs[kc4 + 3][row] = bv.w;
        }
        __syncthreads();

#pragma unroll
        for (int kk = 0; kk < 16; ++kk) {
            ulonglong2 a01 = *(const ulonglong2*)&As[kk][ty * 8];
            ulonglong2 a23 = *(const ulonglong2*)&As[kk][ty * 8 + 4];
            float4 b0 = *(const float4*)&Bs[kk][tx * 8];
            float4 b1 = *(const float4*)&Bs[kk][tx * 8 + 4];
            u64 bd[8];
            bd[0] = dup2(b0.x); bd[1] = dup2(b0.y);
            bd[2] = dup2(b0.z); bd[3] = dup2(b0.w);
            bd[4] = dup2(b1.x); bd[5] = dup2(b1.y);
            bd[6] = dup2(b1.z); bd[7] = dup2(b1.w);
            u64 ap[4] = {a01.x, a01.y, a23.x, a23.y};
#pragma unroll
            for (int i = 0; i < 4; ++i)
#pragma unroll
                for (int q = 0; q < 8; ++q) ffma2(acc[i][q], ap[i], bd[q]);
        }
        __syncthreads();
    }

    float bv[8];
#pragma unroll
    for (int q = 0; q < 8; ++q) {
        bv[q] = bias1[bn + tx * 8 + q];
        if (BIAS2) bv[q] += bias2[bn + tx * 8 + q];
    }
#pragma unroll
    for (int i = 0; i < 4; ++i) {
        float lo[8], hi[8];
#pragma unroll
        for (int q = 0; q < 8; ++q) {
            upk2(acc[i][q], lo[q], hi[q]);
            lo[q] += bv[q]; hi[q] += bv[q];
            if (RELU) { lo[q] = fmaxf(lo[q], 0.0f); hi[q] = fmaxf(hi[q], 0.0f); }
        }
        float* c0 = C + (size_t)(bm + ty * 8 + 2 * i) * N + bn + tx * 8;
        float* c1 = c0 + N;
        *(float4*)(c0 + 0) = make_float4(lo[0], lo[1], lo[2], lo[3]);
        *(float4*)(c0 + 4) = make_float4(lo[4], lo[5], lo[6], lo[7]);
        *(float4*)(c1 + 0) = make_float4(hi[0], hi[1], hi[2], hi[3]);
        *(float4*)(c1 + 4) = make_float4(hi[4], hi[5], hi[6], hi[7]);
    }
}

// ============================================================
// LSTM recurrence: one CTA per env (32 CTAs), 512 threads.
// ============================================================
#define LSTM_SMEM_BYTES (16 * 512 * 16 + 128 * 4 + 512 * 4)

__global__ void __launch_bounds__(512, 1)
lstm_kernel(const float* __restrict__ gx, const float* __restrict__ whh,
            const int* __restrict__ done, const float* __restrict__ h0,
            const float* __restrict__ c0, float* __restrict__ hid)
{
    extern __shared__ float sm[];
    float4* wp4  = (float4*)sm;                    // [16][512] float4
    float*  h_sh = sm + 16 * 512 * 4;              // 128
    float*  act  = h_sh + 128;                     // 512

    const int env = blockIdx.x;
    const int j = threadIdx.x;

    const float* wrow = whh + (size_t)j * 128;
    float wreg[64];
#pragma unroll
    for (int k = 0; k < 64; k += 4) {
        float4 v = *(const float4*)(wrow + k);
        wreg[k] = v.x; wreg[k + 1] = v.y; wreg[k + 2] = v.z; wreg[k + 3] = v.w;
    }
#pragma unroll
    for (int kk = 0; kk < 16; ++kk)
        wp4[kk * 512 + j] = *(const float4*)(wrow + 64 + kk * 4);

    float c = 0.0f, hprev = 0.0f;
    if (j < 128) {
        hprev = h0[env * 128 + j];
        c     = c0[env * 128 + j];
    }
    __syncthreads();

    for (int t = 0; t < TT; ++t) {
        if (j < 128) {
            float m = 1.0f - (float)done[t * BB + env];
            h_sh[j] = hprev * m;
            c *= m;
        }
        __syncthreads();

        float accv = gx[((size_t)t * BB + env) * 512 + j];
#pragma unroll
        for (int k = 0; k < 64; k += 4) {
            float4 hv = *(const float4*)&h_sh[k];
            accv += hv.x * wreg[k] + hv.y * wreg[k + 1]
                  + hv.z * wreg[k + 2] + hv.w * wreg[k + 3];
        }
#pragma unroll
        for (int kk = 0; kk < 16; ++kk) {
            float4 wv = wp4[kk * 512 + j];
            float4 hv = *(const float4*)&h_sh[64 + kk * 4];
            accv += wv.x * hv.x + wv.y * hv.y + wv.z * hv.z + wv.w * hv.w;
        }

        float a;
        if (j < 256 || j >= 384) a = 1.0f / (1.0f + expf(-accv));
        else                     a = tanhf(accv);
        act[j] = a;
        __syncthreads();

        if (j < 128) {
            float ig = act[j],       fg = act[128 + j];
            float gg = act[256 + j], og = act[384 + j];
            c = fg * c + ig * gg;
            hprev = og * tanhf(c);
            hid[((size_t)t * BB + env) * 128 + j] = hprev;
        }
    }
}

// ============================================================
// heads
// ============================================================
__global__ void __launch_bounds__(304, 4)
heads_kernel(const float* __restrict__ hid, const float* __restrict__ wa,
             const float* __restrict__ ba, const float* __restrict__ wc,
             const float* __restrict__ bc, float* __restrict__ out)
{
    __shared__ float wsh[19 * 128];
    __shared__ float hsh[16 * 128];
    __shared__ float bsh[19];

    const int t = threadIdx.x;
    const int rb = blockIdx.x * 16;

    for (int i = t; i < 18 * 128; i += 304) wsh[i] = wa[i];
    for (int i = t; i < 128; i += 304)      wsh[18 * 128 + i] = wc[i];
    for (int i = t; i < 2048; i += 304)     hsh[i] = hid[(size_t)rb * 128 + i];
    if (t < 18) bsh[t] = ba[t];
    if (t == 18) bsh[18] = bc[0];
    __syncthreads();

    const int r = t / 19, cidx = t % 19;
    float accv = bsh[cidx];
    const float* hr = &hsh[r * 128];
    const float* wr = &wsh[cidx * 128];
#pragma unroll
    for (int k = 0; k < 128; k += 4) {
        float4 hv = *(const float4*)(hr + k);
        float4 wv = *(const float4*)(wr + k);
        accv += hv.x * wv.x + hv.y * wv.y + hv.z * wv.z + hv.w * wv.w;
    }
    out[(size_t)(rb + r) * OUTC + cidx] = accv;
}

// ============================================================
// host launcher
// ============================================================
extern "C" void kernel_launch(void* const* d_in, const int* in_sizes, int n_in,
                              void* d_out, int out_size)
{
    const float* x    = (const float*)d_in[0];
    const int*   done = (const int*)  d_in[1];
    const float* h0   = (const float*)d_in[2];
    const float* c0   = (const float*)d_in[3];
    const float* w1   = (const float*)d_in[4];
    const float* b1   = (const float*)d_in[5];
    const float* w2   = (const float*)d_in[6];
    const float* b2   = (const float*)d_in[7];
    const float* w3   = (const float*)d_in[8];
    const float* b3   = (const float*)d_in[9];
    const float* wf   = (const float*)d_in[10];
    const float* bf   = (const float*)d_in[11];
    const float* w_ih = (const float*)d_in[12];
    const float* w_hh = (const float*)d_in[13];
    const float* b_ih = (const float*)d_in[14];
    const float* b_hh = (const float*)d_in[15];
    const float* wa   = (const float*)d_in[16];
    const float* ba   = (const float*)d_in[17];
    const float* wc   = (const float*)d_in[18];
    const float* bc   = (const float*)d_in[19];
    float* out = (float*)d_out;

    float *c1, *c2, *c3, *feat, *gx, *hidp, *w1r, *w2r, *w3r;
    cudaGetSymbolAddress((void**)&c1,   g_c1);
    cudaGetSymbolAddress((void**)&c2,   g_c2);
    cudaGetSymbolAddress((void**)&c3,   g_c3);
    cudaGetSymbolAddress((void**)&feat, g_feat);
    cudaGetSymbolAddress((void**)&gx,   g_gx);
    cudaGetSymbolAddress((void**)&hidp, g_hid);
    cudaGetSymbolAddress((void**)&w1r,  g_w1r);
    cudaGetSymbolAddress((void**)&w2r,  g_w2r);
    cudaGetSymbolAddress((void**)&w3r,  g_w3r);

    const int c1_smem = (28224 + 8192) * 4;             // 145664
    const int c2_smem = (32768 + 12800) * 4;            // 182272
    const int c3_smem = (36864 + 2 * 5184) * 4;         // 188928
    cudaFuncSetAttribute(conv1_kernel, cudaFuncAttributeMaxDynamicSharedMemorySize, c1_smem);
    cudaFuncSetAttribute(conv2_kernel, cudaFuncAttributeMaxDynamicSharedMemorySize, c2_smem);
    cudaFuncSetAttribute(conv3_kernel, cudaFuncAttributeMaxDynamicSharedMemorySize, c3_smem);
    cudaFuncSetAttribute(lstm_kernel,  cudaFuncAttributeMaxDynamicSharedMemorySize, LSTM_SMEM_BYTES);

    // weight reorders (tiny, once per launch)
    reorder_w_kernel<<<(8192  + 255) / 256, 256>>>(w1, w1r, 256, 32, 1.0f / 255.0f);
    reorder_w_kernel<<<(32768 + 255) / 256, 256>>>(w2, w2r, 512, 64, 1.0f);
    reorder_w_kernel<<<(36864 + 255) / 256, 256>>>(w3, w3r, 576, 64, 1.0f);

    conv1_kernel<<<TB, 512, c1_smem>>>(x, w1r, b1, c1);
    conv2_kernel<<<TB / 4, 256, c2_smem>>>(c1, w2r, b2, c2);
    conv3_kernel<<<TB / 4, 256, c3_smem>>>(c2, w3r, b3, c3);

    // feat = relu(c3 @ wf^T + bf)         M=4096 N=512 K=3136
    gemm_kernel<true, false><<<dim3(FEAT / 64, TB / 128), 128>>>(
        c3, wf, bf, nullptr, feat, TB, FEAT, 3136);

    // gx = feat @ w_ih^T + b_ih + b_hh    M=4096 N=512 K=512
    gemm_kernel<false, true><<<dim3(512 / 64, TB / 128), 128>>>(
        feat, w_ih, b_ih, b_hh, gx, TB, 512, FEAT);

    lstm_kernel<<<BB, 512, LSTM_SMEM_BYTES>>>(gx, w_hh, done, h0, c0, hidp);

    heads_kernel<<<TB / 16, 304>>>(hidp, wa, ba, wc, bc, out);
}